// round 5
// baseline (speedup 1.0000x reference)
#include <cuda_runtime.h>
#include <mma.h>

using namespace nvcuda;

#define N_ENTITY 100000
#define N_RELS   500
#define DIM      128
#define NTRIP    250000
#define NBATCH   500000
#define BNEPS    1e-5f
#define OUT_ENT  (N_ENTITY*DIM)

typedef unsigned long long ull;

// ---------------- scratch (static device globals; no allocation) ----------------
__device__ __align__(16) float g_PI[N_ENTITY*256];   // interleaved P0'(=P0+d) | P1 per entity
__device__ __align__(16) float g_Q [N_RELS*DIM];
__device__ __align__(16) float g_Gt [DIM*256];       // fp32 [k][jj] jj<128 -> G0, else G1
__device__ __align__(16) float g_Grt[DIM*DIM];       // [k][j]
__device__ int   g_icntE[N_ENTITY];
__device__ int   g_icntR[N_RELS];
__device__ __align__(16) float g_stats4[512];        // sumE | sumE2 | varR | sumZ2
__device__ __align__(16) float g_d[DIM];
__device__ __align__(16) float g_ac[DIM], g_dc[DIM], g_wt[DIM];
__device__ __align__(16) float g_u0[DIM], g_u1[DIM];
__device__ float g_Sc;
__device__ float g_s0[N_ENTITY], g_s1[N_ENTITY], g_sq[N_RELS];
__device__ float g_ebs[N_ENTITY];
// relation CSR only
__device__ int g_offR[N_RELS], g_curR[N_RELS];
__device__ int g_incR[NTRIP];

// ---------------- helpers ----------------
__device__ __forceinline__ float4 f4add(float4 a, float4 b){ return make_float4(a.x+b.x,a.y+b.y,a.z+b.z,a.w+b.w); }
__device__ __forceinline__ float4 f4sub(float4 a, float4 b){ return make_float4(a.x-b.x,a.y-b.y,a.z-b.z,a.w-b.w); }
__device__ __forceinline__ float4 f4mul(float4 a, float4 b){ return make_float4(a.x*b.x,a.y*b.y,a.z*b.z,a.w*b.w); }
__device__ __forceinline__ float4 f4scale(float s, float4 b){ return make_float4(s*b.x,s*b.y,s*b.z,s*b.w); }
__device__ __forceinline__ float4 ldg4(const float4* p){ return __ldg(p); }
__device__ __forceinline__ float lrexp(float s){ return expf(s >= 0.f ? -s : -0.01f*s); }

__device__ __forceinline__ void red4(float* p, float4 v){
    asm volatile("red.global.add.v4.f32 [%0], {%1, %2, %3, %4};"
        :: "l"(p), "f"(v.x), "f"(v.y), "f"(v.z), "f"(v.w) : "memory");
}

// ---------------- front-end kernels ----------------
__global__ void k_count(const int* __restrict__ trip){
    int i = blockIdx.x*blockDim.x + threadIdx.x;
    if (i < NTRIP){
        atomicAdd(&g_icntE[trip[3*i]], 1);
        atomicAdd(&g_icntE[trip[3*i+1]], 1);
        atomicAdd(&g_icntR[trip[3*i+2]], 1);
    }
}

// fused count-weighted BN0 stats: ent blocks [0,1600), rel blocks [1600,1663)
__global__ void k_stats(const float* __restrict__ E, const float* __restrict__ R){
    int j = threadIdx.x;                 // 128
    if (blockIdx.x < 1600){
        int e0 = blockIdx.x*63, e1 = min(e0+63, N_ENTITY);
        float a1 = 0.f, a2 = 0.f;
        for (int e = e0; e < e1; e++){
            float c = (float)__ldg(&g_icntE[e]);
            float v = __ldg(&E[e*DIM + j]);
            a1 += c*v;
            a2 += c*v*v;
        }
        atomicAdd(&g_stats4[j], a1);
        atomicAdd(&g_stats4[128 + j], a2);
    } else {
        int b = blockIdx.x - 1600;
        int r0 = b*8, r1 = min(r0 + 8, N_RELS);
        float a = 0.f;
        for (int r = r0; r < r1; r++){
            float v = R[r*DIM + j];
            a += (float)g_icntR[r]*v*v;
        }
        atomicAdd(&g_stats4[256 + j], a);
    }
}

// fused bn0 finalize + G materialization
__global__ void k_bn0makeG(const float* __restrict__ a_w, const float* __restrict__ a_b,
                           const float* __restrict__ bn0_g, const float* __restrict__ bn0_b){
    const float inv = 1.f/(float)NBATCH;
    if (blockIdx.x < 128){
        int k = blockIdx.x, jj = threadIdx.x;
        float m  = g_stats4[k]*inv;
        float v  = g_stats4[128 + k]*inv - m*m;
        float rs = rsqrtf(v + BNEPS);
        float a0 = bn0_g[k]*rs;
        float a1 = bn0_g[128 + k]*rs;
        float vr = g_stats4[256 + k]*(1.f/(float)NTRIP);   // mean of r-cols is exactly 0
        float ar = bn0_g[256 + k]*rsqrtf(vr + BNEPS);
        int j = jj & 127;
        int half = jj >> 7;
        float al = half ? a1 : a0;
        int col  = half ? 128 + k : k;
        g_Gt[k*256 + jj] = a_w[j*384 + col]*al;
        if (jj < 128) g_Grt[k*128 + jj] = a_w[jj*384 + 256 + k]*ar;
    } else {
        __shared__ float dsh[384];
        int j = threadIdx.x;
        if (j < 128){
            float m  = g_stats4[j]*inv;
            float v  = g_stats4[128 + j]*inv - m*m;
            float rs = rsqrtf(v + BNEPS);
            float a0 = bn0_g[j]*rs;
            float a1 = bn0_g[128 + j]*rs;
            dsh[j]       = bn0_b[j]       - m*a0;
            dsh[128 + j] = bn0_b[128 + j] - m*a1;
            dsh[256 + j] = bn0_b[256 + j];
        }
        __syncthreads();
        if (j < 128){
            float acc = a_b[j];
            #pragma unroll 8
            for (int k = 0; k < 384; k++) acc += a_w[j*384 + k]*dsh[k];
            g_d[j] = acc;
        }
    }
}

// ---------------- WMMA tf32 split-precision P GEMM: P = E*G^T + (jh==0 ? d : 0) ----------------
// smem layout (floats): AsH[4096] AsL[4096] BsH[4096] BsL[4096] drep[2048]
// epilogue reuses [0,16384) as the 128x128 C tile.
__global__ void __launch_bounds__(256) k_pgemm_tc(const float* __restrict__ E){
    extern __shared__ float smf[];
    float* AsH  = smf;            // [m][k] ldm 32
    float* AsL  = smf + 4096;
    float* BsH  = smf + 8192;     // [k][n] ldm 128
    float* BsL  = smf + 12288;
    float* drep = smf + 16384;    // [16][128], rows identical = d
    int tid = threadIdx.x;
    int wid = tid >> 5;
    int wr = wid >> 2, wc = wid & 3;     // warp tile: rows wr*64..+64, cols wc*32..+32
    int e0 = blockIdx.x*128, jh = blockIdx.y;

    #pragma unroll
    for (int i = 0; i < 8; i++){
        int idx = tid*8 + i;             // 0..2047
        drep[idx] = g_d[idx & 127];
    }
    __syncthreads();

    wmma::fragment<wmma::accumulator,16,16,8,float> c[4][2];
    if (jh == 0){
        #pragma unroll
        for (int mi = 0; mi < 4; mi++)
            #pragma unroll
            for (int ni = 0; ni < 2; ni++)
                wmma::load_matrix_sync(c[mi][ni], drep + wc*32 + ni*16, 128, wmma::mem_row_major);
    } else {
        #pragma unroll
        for (int mi = 0; mi < 4; mi++)
            #pragma unroll
            for (int ni = 0; ni < 2; ni++)
                wmma::fill_fragment(c[mi][ni], 0.f);
    }

    for (int kt = 0; kt < 128; kt += 32){
        __syncthreads();
        // A tile: 128x32 fp32 -> tf32 hi/lo
        #pragma unroll
        for (int i = 0; i < 16; i++){
            int idx = tid*16 + i;        // = m*32 + k
            int m = idx >> 5, k = idx & 31;
            float v = 0.f;
            int e = e0 + m;
            if (e < N_ENTITY) v = __ldg(&E[(size_t)e*DIM + kt + k]);
            float h = wmma::__float_to_tf32(v);
            AsH[idx] = h;
            AsL[idx] = wmma::__float_to_tf32(v - h);
        }
        // B tile: 32x128 from g_Gt -> tf32 hi/lo
        #pragma unroll
        for (int i = 0; i < 16; i++){
            int idx = tid*16 + i;        // = k*128 + n
            int k = idx >> 7, n = idx & 127;
            float v = __ldg(&g_Gt[(kt + k)*256 + jh*128 + n]);
            float h = wmma::__float_to_tf32(v);
            BsH[idx] = h;
            BsL[idx] = wmma::__float_to_tf32(v - h);
        }
        __syncthreads();

        wmma::fragment<wmma::matrix_a,16,16,8,wmma::precision::tf32,wmma::row_major> a[4];
        wmma::fragment<wmma::matrix_b,16,16,8,wmma::precision::tf32,wmma::row_major> b[2];
        #pragma unroll
        for (int ch = 0; ch < 3; ch++){
            const float* Ap = (ch == 2) ? AsL : AsH;
            const float* Bp = (ch == 1) ? BsL : BsH;
            #pragma unroll
            for (int k8 = 0; k8 < 4; k8++){
                #pragma unroll
                for (int mi = 0; mi < 4; mi++)
                    wmma::load_matrix_sync(a[mi], Ap + (wr*64 + mi*16)*32 + k8*8, 32);
                #pragma unroll
                for (int ni = 0; ni < 2; ni++)
                    wmma::load_matrix_sync(b[ni], Bp + (k8*8)*128 + wc*32 + ni*16, 128);
                #pragma unroll
                for (int mi = 0; mi < 4; mi++)
                    #pragma unroll
                    for (int ni = 0; ni < 2; ni++)
                        wmma::mma_sync(c[mi][ni], a[mi], b[ni], c[mi][ni]);
            }
        }
    }
    __syncthreads();
    // store C (128x128) into smem, then guarded vectorized global write
    #pragma unroll
    for (int mi = 0; mi < 4; mi++)
        #pragma unroll
        for (int ni = 0; ni < 2; ni++)
            wmma::store_matrix_sync(smf + (wr*64 + mi*16)*128 + wc*32 + ni*16,
                                    c[mi][ni], 128, wmma::mem_row_major);
    __syncthreads();
    {
        int row = tid >> 1, half = tid & 1;
        int e = e0 + row;
        if (e < N_ENTITY){
            const float4* src = (const float4*)(smf + row*128 + half*64);
            float4* dst = (float4*)&g_PI[(size_t)e*256 + jh*128 + half*64];
            #pragma unroll
            for (int i = 0; i < 16; i++) dst[i] = src[i];
        }
    }
}

__global__ void k_qgemm(const float* __restrict__ R){
    __shared__ float Rs[128];
    int rho = blockIdx.x, j = threadIdx.x;
    Rs[j] = R[rho*DIM + j];
    __syncthreads();
    float acc = 0.f;
    #pragma unroll 8
    for (int k = 0; k < 128; k++) acc += Rs[k]*g_Grt[k*128 + j];
    g_Q[rho*DIM + j] = acc;
}

// ---- relation CSR (500 segments): scan + fill ----
__global__ void k_scanR(){                         // 1 x 512
    __shared__ int sh[512];
    int t = threadIdx.x;
    int v = (t < N_RELS) ? g_icntR[t] : 0;
    sh[t] = v; __syncthreads();
    #pragma unroll
    for (int off = 1; off < 512; off <<= 1){
        int add = (t >= off) ? sh[t - off] : 0;
        __syncthreads();
        sh[t] += add;
        __syncthreads();
    }
    if (t < N_RELS){ int o = sh[t] - v; g_offR[t] = o; g_curR[t] = o; }
}

__global__ void k_fillR(const int* __restrict__ trip){
    int i = blockIdx.x*blockDim.x + threadIdx.x;
    if (i < NTRIP){
        int pr = atomicAdd(&g_curR[trip[3*i+2]], 1);
        g_incR[pr] = i;
    }
}

// pass D1: accumulate Σz^2 (warp per 2 triplets for MLP). Σz is analytic.
__global__ void k_bn1stats(const int* __restrict__ trip){
    int lane = threadIdx.x & 31;
    int warp = (blockIdx.x*blockDim.x + threadIdx.x) >> 5;
    int nw   = (gridDim.x*blockDim.x) >> 5;
    const float4* PI4 = (const float4*)g_PI;
    const float4* Q4  = (const float4*)g_Q;
    float4 s2v = make_float4(0.f,0.f,0.f,0.f);
    for (int i0 = warp*2; i0 < NTRIP; i0 += nw*2){
        int i1 = i0 + 1;   // NTRIP is even -> always valid
        int a0 = trip[3*i0], a1 = trip[3*i0+1], a2 = trip[3*i0+2];
        int b0 = trip[3*i1], b1 = trip[3*i1+1], b2 = trip[3*i1+2];
        float4 pa00 = ldg4(&PI4[a0*64 + lane]);
        float4 pa10 = ldg4(&PI4[a0*64 + 32 + lane]);
        float4 pa01 = ldg4(&PI4[a1*64 + lane]);
        float4 pa11 = ldg4(&PI4[a1*64 + 32 + lane]);
        float4 qa   = ldg4(&Q4 [a2*32 + lane]);
        float4 pb00 = ldg4(&PI4[b0*64 + lane]);
        float4 pb10 = ldg4(&PI4[b0*64 + 32 + lane]);
        float4 pb01 = ldg4(&PI4[b1*64 + lane]);
        float4 pb11 = ldg4(&PI4[b1*64 + 32 + lane]);
        float4 qb   = ldg4(&Q4 [b2*32 + lane]);
        float4 zf = f4add(f4add(pa00, pa11), qa);
        float4 zb = f4sub(f4add(pa01, pa10), qa);
        s2v = f4add(s2v, f4add(f4mul(zf,zf), f4mul(zb,zb)));
        zf = f4add(f4add(pb00, pb11), qb);
        zb = f4sub(f4add(pb01, pb10), qb);
        s2v = f4add(s2v, f4add(f4mul(zf,zf), f4mul(zb,zb)));
    }
    int j4 = lane*4;
    atomicAdd(&g_stats4[384 + j4 + 0], s2v.x);
    atomicAdd(&g_stats4[384 + j4 + 1], s2v.y);
    atomicAdd(&g_stats4[384 + j4 + 2], s2v.z);
    atomicAdd(&g_stats4[384 + j4 + 3], s2v.w);
}

__global__ void k_bn1fin(const float* __restrict__ a2_w, const float* __restrict__ a2_b,
                         const float* __restrict__ bn1_g, const float* __restrict__ bn1_b){
    __shared__ float wts[128];
    __shared__ float red[128];
    int j = threadIdx.x;
    // analytic Σz: Q terms cancel between fwd/bwd rows
    float sz = 0.f;
    #pragma unroll 4
    for (int k = 0; k < 128; k++){
        float se = g_stats4[k];
        sz += se*(g_Gt[k*256 + j] + g_Gt[k*256 + 128 + j]);
    }
    float dj = g_d[j];
    sz += 2.f*(float)NTRIP*dj;
    const float inv = 1.f/(float)NBATCH;
    float mz = sz*inv;
    float vz = g_stats4[384 + j]*inv - mz*mz;
    float ac = bn1_g[j]*rsqrtf(vz + BNEPS);
    float dc = bn1_b[j] - mz*ac;
    g_ac[j] = ac; g_dc[j] = dc;
    float w = a2_w[j]*ac;
    g_wt[j] = w;
    wts[j] = w;
    red[j] = w*dj + a2_w[j]*dc;
    __syncthreads();
    float u0 = 0.f, u1 = 0.f;
    #pragma unroll 4
    for (int jj = 0; jj < 128; jj++){
        float wv = wts[jj];
        u0 += wv*g_Gt[j*256 + jj];
        u1 += wv*g_Gt[j*256 + 128 + jj];
    }
    g_u0[j] = u0; g_u1[j] = u1;
    for (int s = 64; s > 0; s >>= 1){
        if (j < s) red[j] += red[j+s];
        __syncthreads();
    }
    if (j == 0) g_Sc = red[0] + a2_b[0];
}

// s0[e]=E[e]·u0, s1[e]=E[e]·u1 (ent jobs), sq[r]=wt·Q[r] (rel jobs)
__global__ void k_sentsq(const float* __restrict__ E){
    int lane = threadIdx.x & 31;
    int warp = (blockIdx.x*blockDim.x + threadIdx.x) >> 5;
    int nw   = (gridDim.x*blockDim.x) >> 5;
    float4 u04 = ((const float4*)g_u0)[lane];
    float4 u14 = ((const float4*)g_u1)[lane];
    const float4* E4 = (const float4*)E;
    const float4* Q4 = (const float4*)g_Q;
    for (int job = warp; job < N_ENTITY + N_RELS; job += nw){
        if (job < N_ENTITY){
            float4 v = ldg4(&E4[job*32 + lane]);
            float d0 = v.x*u04.x + v.y*u04.y + v.z*u04.z + v.w*u04.w;
            float d1 = v.x*u14.x + v.y*u14.y + v.z*u14.z + v.w*u14.w;
            #pragma unroll
            for (int off = 16; off > 0; off >>= 1){
                d0 += __shfl_down_sync(0xffffffffu, d0, off);
                d1 += __shfl_down_sync(0xffffffffu, d1, off);
            }
            if (lane == 0){ g_s0[job] = d0; g_s1[job] = d1; }
        } else {
            int r = job - N_ENTITY;
            float4 w4 = ((const float4*)g_wt)[lane];
            float4 p  = Q4[r*32 + lane];
            float d0 = p.x*w4.x + p.y*w4.y + p.z*w4.z + p.w*w4.w;
            #pragma unroll
            for (int off = 16; off > 0; off >>= 1)
                d0 += __shfl_down_sync(0xffffffffu, d0, off);
            if (lane == 0) g_sq[r] = d0;
        }
    }
}

// pass D2: entity scatter (warp per 2 triplets); relation handled by CSR gather in k_rel
__global__ void k_scatter(const int* __restrict__ trip, float* __restrict__ out){
    int lane = threadIdx.x & 31;
    int warp = (blockIdx.x*blockDim.x + threadIdx.x) >> 5;
    int nw   = (gridDim.x*blockDim.x) >> 5;
    float Sc = g_Sc;
    const float4* PI4 = (const float4*)g_PI;
    const float4* Q4  = (const float4*)g_Q;
    for (int i0 = warp*2; i0 < NTRIP; i0 += nw*2){
        int i1 = i0 + 1;
        int a0 = trip[3*i0], a1 = trip[3*i0+1], a2 = trip[3*i0+2];
        int b0 = trip[3*i1], b1 = trip[3*i1+1], b2 = trip[3*i1+2];
        float sqa = __ldg(&g_sq[a2]), sqb = __ldg(&g_sq[b2]);
        float sfa = __ldg(&g_s0[a0]) + __ldg(&g_s1[a1]) + sqa + Sc;
        float sba = __ldg(&g_s0[a1]) + __ldg(&g_s1[a0]) - sqa + Sc;
        float sfb = __ldg(&g_s0[b0]) + __ldg(&g_s1[b1]) + sqb + Sc;
        float sbb = __ldg(&g_s0[b1]) + __ldg(&g_s1[b0]) - sqb + Sc;
        float efa = lrexp(sfa), eba = lrexp(sba);
        float efb = lrexp(sfb), ebb = lrexp(sbb);
        float4 pa00 = ldg4(&PI4[a0*64 + lane]);
        float4 pa10 = ldg4(&PI4[a0*64 + 32 + lane]);
        float4 pa01 = ldg4(&PI4[a1*64 + lane]);
        float4 pa11 = ldg4(&PI4[a1*64 + 32 + lane]);
        float4 qa   = ldg4(&Q4 [a2*32 + lane]);
        float4 pb00 = ldg4(&PI4[b0*64 + lane]);
        float4 pb10 = ldg4(&PI4[b0*64 + 32 + lane]);
        float4 pb01 = ldg4(&PI4[b1*64 + lane]);
        float4 pb11 = ldg4(&PI4[b1*64 + 32 + lane]);
        float4 qb   = ldg4(&Q4 [b2*32 + lane]);
        float4 zfa = f4add(f4add(pa00, pa11), qa);
        float4 zba = f4sub(f4add(pa01, pa10), qa);
        float4 zfb = f4add(f4add(pb00, pb11), qb);
        float4 zbb = f4sub(f4add(pb01, pb10), qb);
        red4(out + (size_t)a0*DIM + lane*4, f4scale(efa, zfa));
        red4(out + (size_t)a1*DIM + lane*4, f4scale(eba, zba));
        red4(out + (size_t)b0*DIM + lane*4, f4scale(efb, zfb));
        red4(out + (size_t)b1*DIM + lane*4, f4scale(ebb, zbb));
        if (lane == 0){
            atomicAdd(&g_ebs[a0], efa);
            atomicAdd(&g_ebs[a1], eba);
            atomicAdd(&g_ebs[b0], efb);
            atomicAdd(&g_ebs[b1], ebb);
        }
    }
}

__global__ void k_fin_ent(float* __restrict__ out){
    float4* O = (float4*)out;
    int i0 = blockIdx.x*blockDim.x + threadIdx.x;
    int stride = gridDim.x*blockDim.x;
    for (int idx = i0; idx < N_ENTITY*32; idx += stride){
        int e = idx >> 5, l = idx & 31;
        float ebv = g_ebs[e];
        float den = (ebv == 0.f) ? 1e-12f : ebv;
        float inv = 1.f/den;
        float4 z = O[idx];
        float4 a = ((const float4*)g_ac)[l];
        float4 d = ((const float4*)g_dc)[l];
        z.x = (a.x*z.x + d.x*ebv)*inv;
        z.y = (a.y*z.y + d.y*ebv)*inv;
        z.z = (a.z*z.z + d.z*ebv)*inv;
        z.w = (a.w*z.w + d.w*ebv)*inv;
        O[idx] = z;
    }
}

// atomic-free relation aggregation: block per relation (8 warps), CSR gather
__global__ void __launch_bounds__(256) k_rel(const int* __restrict__ trip, float* __restrict__ out){
    __shared__ float sm[8][128];
    __shared__ float sw[8];
    int r = blockIdx.x;
    int lane = threadIdx.x & 31;
    int wrp  = threadIdx.x >> 5;
    const float4* PI4 = (const float4*)g_PI;
    float4 q = ((const float4*)g_Q)[r*32 + lane];
    float sqv = g_sq[r];
    float Sc  = g_Sc;
    int base = g_offR[r], cnt = g_icntR[r];
    float4 acc = make_float4(0.f,0.f,0.f,0.f);
    float wsum = 0.f;
    for (int k = wrp; k < cnt; k += 8){
        int i = g_incR[base + k];
        int t0 = trip[3*i], t1 = trip[3*i+1];
        float s = __ldg(&g_s0[t0]) + __ldg(&g_s1[t1]) + sqv + Sc;
        float w = lrexp(s);
        float4 pa = ldg4(&PI4[t0*64 + lane]);        // P0'[t0] (d folded)
        float4 pb = ldg4(&PI4[t1*64 + 32 + lane]);   // P1[t1]
        acc.x += w*(pa.x + pb.x + q.x);
        acc.y += w*(pa.y + pb.y + q.y);
        acc.z += w*(pa.z + pb.z + q.z);
        acc.w += w*(pa.w + pb.w + q.w);
        wsum += w;
    }
    *(float4*)&sm[wrp][lane*4] = acc;
    #pragma unroll
    for (int off = 16; off > 0; off >>= 1) wsum += __shfl_down_sync(0xffffffffu, wsum, off);
    if (lane == 0) sw[wrp] = wsum;
    __syncthreads();
    int t = threadIdx.x;
    if (t < 128){
        float tot = 0.f;
        #pragma unroll
        for (int w = 0; w < 8; w++) tot += sm[w][t];
        float W = 0.f;
        #pragma unroll
        for (int w = 0; w < 8; w++) W += sw[w];
        float invc = 1.f/fmaxf((float)cnt, 1.f);
        out[OUT_ENT + (size_t)r*DIM + t] = (g_ac[t]*tot + g_dc[t]*W)*invc;
    }
}

// ---------------- launcher ----------------
extern "C" void kernel_launch(void* const* d_in, const int* in_sizes, int n_in,
                              void* d_out, int out_size){
    const int*   trip  = (const int*)  d_in[0];
    const float* E     = (const float*)d_in[1];
    const float* R     = (const float*)d_in[2];
    const float* a_w   = (const float*)d_in[3];
    const float* a_b   = (const float*)d_in[4];
    const float* a2_w  = (const float*)d_in[5];
    const float* a2_b  = (const float*)d_in[6];
    const float* bn0_g = (const float*)d_in[7];
    const float* bn0_b = (const float*)d_in[8];
    const float* bn1_g = (const float*)d_in[9];
    const float* bn1_b = (const float*)d_in[10];
    float* out = (float*)d_out;

    cudaFuncSetAttribute(k_pgemm_tc, cudaFuncAttributeMaxDynamicSharedMemorySize, 73728);

    void *pIcE, *pIcR, *pSt, *pEbs;
    cudaGetSymbolAddress(&pIcE, g_icntE);
    cudaGetSymbolAddress(&pIcR, g_icntR);
    cudaGetSymbolAddress(&pSt,  g_stats4);
    cudaGetSymbolAddress(&pEbs, g_ebs);
    cudaMemsetAsync(pIcE, 0, N_ENTITY*sizeof(int));
    cudaMemsetAsync(pIcR, 0, N_RELS*sizeof(int));
    cudaMemsetAsync(pSt,  0, 512*sizeof(float));
    cudaMemsetAsync(pEbs, 0, N_ENTITY*sizeof(float));
    cudaMemsetAsync(out,  0, (size_t)OUT_ENT*sizeof(float));

    k_count<<<(NTRIP + 255)/256, 256>>>(trip);
    k_stats<<<1663, 128>>>(E, R);
    k_bn0makeG<<<129, 256>>>(a_w, a_b, bn0_g, bn0_b);
    k_pgemm_tc<<<dim3(782, 2), 256, 73728>>>(E);
    k_qgemm<<<N_RELS, 128>>>(R);
    k_scanR<<<1, 512>>>();
    k_fillR<<<(NTRIP + 255)/256, 256>>>(trip);
    k_bn1stats<<<2048, 256>>>(trip);
    k_bn1fin<<<1, 128>>>(a2_w, a2_b, bn1_g, bn1_b);
    k_sentsq<<<800, 256>>>(E);
    k_scatter<<<2048, 256>>>(trip, out);
    k_fin_ent<<<2048, 256>>>(out);
    k_rel<<<N_RELS, 256>>>(trip, out);
}

// round 6
// speedup vs baseline: 1.6512x; 1.6512x over previous
#include <cuda_runtime.h>

#define N_ENTITY 100000
#define N_RELS   500
#define DIM      128
#define NTRIP    250000
#define NBATCH   500000
#define BNEPS    1e-5f
#define OUT_ENT  (N_ENTITY*DIM)

typedef unsigned long long ull;

// ---------------- scratch (static device globals; no allocation) ----------------
__device__ __align__(16) float g_PI[N_ENTITY*256];   // interleaved P0'(=P0+d) | P1 per entity
__device__ __align__(16) float g_Q [N_RELS*DIM];
__device__ __align__(16) float g_Gt [DIM*256];       // fp32 [k][jj] jj<128 -> G0, else G1
__device__ __align__(16) float g_Grt[DIM*DIM];       // [k][j]
__device__ int   g_icntE[N_ENTITY];
__device__ int   g_icntR[N_RELS];
__device__ __align__(16) float g_stats4[512];        // sumE | sumE2 | varR | sumZ2
__device__ __align__(16) float g_d[DIM];
__device__ __align__(16) float g_ac[DIM], g_dc[DIM], g_wt[DIM];
__device__ __align__(16) float g_u0[DIM], g_u1[DIM];
__device__ float g_Sc;
__device__ float g_s0[N_ENTITY], g_s1[N_ENTITY], g_sq[N_RELS];
__device__ float g_ebs[N_ENTITY];
// relation CSR only
__device__ int g_offR[N_RELS], g_curR[N_RELS];
__device__ int g_incR[NTRIP];

// ---------------- helpers ----------------
__device__ __forceinline__ float4 f4add(float4 a, float4 b){ return make_float4(a.x+b.x,a.y+b.y,a.z+b.z,a.w+b.w); }
__device__ __forceinline__ float4 f4sub(float4 a, float4 b){ return make_float4(a.x-b.x,a.y-b.y,a.z-b.z,a.w-b.w); }
__device__ __forceinline__ float4 f4mul(float4 a, float4 b){ return make_float4(a.x*b.x,a.y*b.y,a.z*b.z,a.w*b.w); }
__device__ __forceinline__ float4 f4scale(float s, float4 b){ return make_float4(s*b.x,s*b.y,s*b.z,s*b.w); }
__device__ __forceinline__ float4 ldg4(const float4* p){ return __ldg(p); }
__device__ __forceinline__ float lrexp(float s){ return expf(s >= 0.f ? -s : -0.01f*s); }

__device__ __forceinline__ void red4(float* p, float4 v){
    asm volatile("red.global.add.v4.f32 [%0], {%1, %2, %3, %4};"
        :: "l"(p), "f"(v.x), "f"(v.y), "f"(v.z), "f"(v.w) : "memory");
}

// ---------------- front-end kernels ----------------
__global__ void k_count(const int* __restrict__ trip){
    int i = blockIdx.x*blockDim.x + threadIdx.x;
    if (i < NTRIP){
        atomicAdd(&g_icntE[trip[3*i]], 1);
        atomicAdd(&g_icntE[trip[3*i+1]], 1);
        atomicAdd(&g_icntR[trip[3*i+2]], 1);
    }
}

// fused count-weighted BN0 stats: ent blocks [0,1600), rel blocks [1600,1663)
__global__ void k_stats(const float* __restrict__ E, const float* __restrict__ R){
    int j = threadIdx.x;                 // 128
    if (blockIdx.x < 1600){
        int e0 = blockIdx.x*63, e1 = min(e0+63, N_ENTITY);
        float a1 = 0.f, a2 = 0.f;
        for (int e = e0; e < e1; e++){
            float c = (float)__ldg(&g_icntE[e]);
            float v = __ldg(&E[e*DIM + j]);
            a1 += c*v;
            a2 += c*v*v;
        }
        atomicAdd(&g_stats4[j], a1);
        atomicAdd(&g_stats4[128 + j], a2);
    } else {
        int b = blockIdx.x - 1600;
        int r0 = b*8, r1 = min(r0 + 8, N_RELS);
        float a = 0.f;
        for (int r = r0; r < r1; r++){
            float v = R[r*DIM + j];
            a += (float)g_icntR[r]*v*v;
        }
        atomicAdd(&g_stats4[256 + j], a);
    }
}

// fused bn0 finalize + G materialization
__global__ void k_bn0makeG(const float* __restrict__ a_w, const float* __restrict__ a_b,
                           const float* __restrict__ bn0_g, const float* __restrict__ bn0_b){
    const float inv = 1.f/(float)NBATCH;
    if (blockIdx.x < 128){
        int k = blockIdx.x, jj = threadIdx.x;
        float m  = g_stats4[k]*inv;
        float v  = g_stats4[128 + k]*inv - m*m;
        float rs = rsqrtf(v + BNEPS);
        float a0 = bn0_g[k]*rs;
        float a1 = bn0_g[128 + k]*rs;
        float vr = g_stats4[256 + k]*(1.f/(float)NTRIP);   // mean of r-cols is exactly 0
        float ar = bn0_g[256 + k]*rsqrtf(vr + BNEPS);
        int j = jj & 127;
        int half = jj >> 7;
        float al = half ? a1 : a0;
        int col  = half ? 128 + k : k;
        g_Gt[k*256 + jj] = a_w[j*384 + col]*al;
        if (jj < 128) g_Grt[k*128 + jj] = a_w[jj*384 + 256 + k]*ar;
    } else {
        __shared__ float dsh[384];
        int j = threadIdx.x;
        if (j < 128){
            float m  = g_stats4[j]*inv;
            float v  = g_stats4[128 + j]*inv - m*m;
            float rs = rsqrtf(v + BNEPS);
            float a0 = bn0_g[j]*rs;
            float a1 = bn0_g[128 + j]*rs;
            dsh[j]       = bn0_b[j]       - m*a0;
            dsh[128 + j] = bn0_b[128 + j] - m*a1;
            dsh[256 + j] = bn0_b[256 + j];
        }
        __syncthreads();
        if (j < 128){
            float acc = a_b[j];
            #pragma unroll 8
            for (int k = 0; k < 384; k++) acc += a_w[j*384 + k]*dsh[k];
            g_d[j] = acc;
        }
    }
}

// P = E * G^T into interleaved layout; d folded into P0 half. f32x2 packed FMA.
// launch_bounds(256,2): cap regs at 128 so 2 CTAs/SM (round-3 ncu: occ 12.4% was the limiter).
__global__ void __launch_bounds__(256, 2) k_pgemm(const float* __restrict__ E){
    __shared__ float As[128*32];
    __shared__ float Bs[32*128];
    int tid = threadIdx.x;
    int tx = tid & 15, ty = tid >> 4;
    int e0 = blockIdx.x*128;
    int jh = blockIdx.y;

    ull acc2[8][4];
    #pragma unroll
    for (int i = 0; i < 8; i++)
        #pragma unroll
        for (int r = 0; r < 4; r++) acc2[i][r] = 0ull;

    for (int kt = 0; kt < 128; kt += 32){
        #pragma unroll
        for (int i = 0; i < 4; i++){
            int lin = tid + i*256;           // float4 index
            int m  = lin >> 3;
            int k4 = (lin & 7) << 2;
            float4 v = make_float4(0.f,0.f,0.f,0.f);
            if (e0 + m < N_ENTITY) v = *(const float4*)&E[(e0+m)*DIM + kt + k4];
            *(float4*)&As[m*32 + k4] = v;
        }
        #pragma unroll
        for (int i = 0; i < 4; i++){
            int lin = tid + i*256;
            int k  = lin >> 5;
            int j4 = (lin & 31) << 2;
            *(float4*)&Bs[k*128 + j4] = *(const float4*)&g_Gt[(kt+k)*256 + jh*128 + j4];
        }
        __syncthreads();
        #pragma unroll
        for (int k = 0; k < 32; k++){
            double2 bl0 = *(const double2*)&Bs[k*128 + tx*8];
            double2 bl1 = *(const double2*)&Bs[k*128 + tx*8 + 4];
            ull b2[4];
            b2[0] = __double_as_longlong(bl0.x);
            b2[1] = __double_as_longlong(bl0.y);
            b2[2] = __double_as_longlong(bl1.x);
            b2[3] = __double_as_longlong(bl1.y);
            #pragma unroll
            for (int i = 0; i < 8; i++){
                unsigned ab = __float_as_uint(As[(ty*8 + i)*32 + k]);
                ull a2;
                asm("mov.b64 %0, {%1, %1};" : "=l"(a2) : "r"(ab));
                #pragma unroll
                for (int r = 0; r < 4; r++)
                    asm("fma.rn.f32x2 %0, %1, %2, %0;" : "+l"(acc2[i][r]) : "l"(a2), "l"(b2[r]));
            }
        }
        __syncthreads();
    }
    float4 dA = make_float4(0,0,0,0), dB = make_float4(0,0,0,0);
    if (jh == 0){
        dA = *(const float4*)&g_d[tx*8];
        dB = *(const float4*)&g_d[tx*8 + 4];
    }
    #pragma unroll
    for (int i = 0; i < 8; i++){
        int e = e0 + ty*8 + i;
        if (e < N_ENTITY){
            float4 v0, v1;
            v0.x = __uint_as_float((unsigned)(acc2[i][0]))       + dA.x;
            v0.y = __uint_as_float((unsigned)(acc2[i][0] >> 32)) + dA.y;
            v0.z = __uint_as_float((unsigned)(acc2[i][1]))       + dA.z;
            v0.w = __uint_as_float((unsigned)(acc2[i][1] >> 32)) + dA.w;
            v1.x = __uint_as_float((unsigned)(acc2[i][2]))       + dB.x;
            v1.y = __uint_as_float((unsigned)(acc2[i][2] >> 32)) + dB.y;
            v1.z = __uint_as_float((unsigned)(acc2[i][3]))       + dB.z;
            v1.w = __uint_as_float((unsigned)(acc2[i][3] >> 32)) + dB.w;
            *(float4*)&g_PI[(size_t)e*256 + jh*128 + tx*8]     = v0;
            *(float4*)&g_PI[(size_t)e*256 + jh*128 + tx*8 + 4] = v1;
        }
    }
}

__global__ void k_qgemm(const float* __restrict__ R){
    __shared__ float Rs[128];
    int rho = blockIdx.x, j = threadIdx.x;
    Rs[j] = R[rho*DIM + j];
    __syncthreads();
    float acc = 0.f;
    #pragma unroll 8
    for (int k = 0; k < 128; k++) acc += Rs[k]*g_Grt[k*128 + j];
    g_Q[rho*DIM + j] = acc;
}

// ---- relation CSR (500 segments): scan + fill ----
__global__ void k_scanR(){                         // 1 x 512
    __shared__ int sh[512];
    int t = threadIdx.x;
    int v = (t < N_RELS) ? g_icntR[t] : 0;
    sh[t] = v; __syncthreads();
    #pragma unroll
    for (int off = 1; off < 512; off <<= 1){
        int add = (t >= off) ? sh[t - off] : 0;
        __syncthreads();
        sh[t] += add;
        __syncthreads();
    }
    if (t < N_RELS){ int o = sh[t] - v; g_offR[t] = o; g_curR[t] = o; }
}

__global__ void k_fillR(const int* __restrict__ trip){
    int i = blockIdx.x*blockDim.x + threadIdx.x;
    if (i < NTRIP){
        int pr = atomicAdd(&g_curR[trip[3*i+2]], 1);
        g_incR[pr] = i;
    }
}

// pass D1: accumulate Σz^2 (warp per 2 triplets for MLP). Σz is analytic.
__global__ void k_bn1stats(const int* __restrict__ trip){
    int lane = threadIdx.x & 31;
    int warp = (blockIdx.x*blockDim.x + threadIdx.x) >> 5;
    int nw   = (gridDim.x*blockDim.x) >> 5;
    const float4* PI4 = (const float4*)g_PI;
    const float4* Q4  = (const float4*)g_Q;
    float4 s2v = make_float4(0.f,0.f,0.f,0.f);
    for (int i0 = warp*2; i0 < NTRIP; i0 += nw*2){
        int i1 = i0 + 1;   // NTRIP is even -> always valid
        int a0 = trip[3*i0], a1 = trip[3*i0+1], a2 = trip[3*i0+2];
        int b0 = trip[3*i1], b1 = trip[3*i1+1], b2 = trip[3*i1+2];
        float4 pa00 = ldg4(&PI4[a0*64 + lane]);
        float4 pa10 = ldg4(&PI4[a0*64 + 32 + lane]);
        float4 pa01 = ldg4(&PI4[a1*64 + lane]);
        float4 pa11 = ldg4(&PI4[a1*64 + 32 + lane]);
        float4 qa   = ldg4(&Q4 [a2*32 + lane]);
        float4 pb00 = ldg4(&PI4[b0*64 + lane]);
        float4 pb10 = ldg4(&PI4[b0*64 + 32 + lane]);
        float4 pb01 = ldg4(&PI4[b1*64 + lane]);
        float4 pb11 = ldg4(&PI4[b1*64 + 32 + lane]);
        float4 qb   = ldg4(&Q4 [b2*32 + lane]);
        float4 zf = f4add(f4add(pa00, pa11), qa);
        float4 zb = f4sub(f4add(pa01, pa10), qa);
        s2v = f4add(s2v, f4add(f4mul(zf,zf), f4mul(zb,zb)));
        zf = f4add(f4add(pb00, pb11), qb);
        zb = f4sub(f4add(pb01, pb10), qb);
        s2v = f4add(s2v, f4add(f4mul(zf,zf), f4mul(zb,zb)));
    }
    int j4 = lane*4;
    atomicAdd(&g_stats4[384 + j4 + 0], s2v.x);
    atomicAdd(&g_stats4[384 + j4 + 1], s2v.y);
    atomicAdd(&g_stats4[384 + j4 + 2], s2v.z);
    atomicAdd(&g_stats4[384 + j4 + 3], s2v.w);
}

__global__ void k_bn1fin(const float* __restrict__ a2_w, const float* __restrict__ a2_b,
                         const float* __restrict__ bn1_g, const float* __restrict__ bn1_b){
    __shared__ float wts[128];
    __shared__ float red[128];
    int j = threadIdx.x;
    // analytic Σz: Q terms cancel between fwd/bwd rows
    float sz = 0.f;
    #pragma unroll 4
    for (int k = 0; k < 128; k++){
        float se = g_stats4[k];
        sz += se*(g_Gt[k*256 + j] + g_Gt[k*256 + 128 + j]);
    }
    float dj = g_d[j];
    sz += 2.f*(float)NTRIP*dj;
    const float inv = 1.f/(float)NBATCH;
    float mz = sz*inv;
    float vz = g_stats4[384 + j]*inv - mz*mz;
    float ac = bn1_g[j]*rsqrtf(vz + BNEPS);
    float dc = bn1_b[j] - mz*ac;
    g_ac[j] = ac; g_dc[j] = dc;
    float w = a2_w[j]*ac;
    g_wt[j] = w;
    wts[j] = w;
    red[j] = w*dj + a2_w[j]*dc;
    __syncthreads();
    float u0 = 0.f, u1 = 0.f;
    #pragma unroll 4
    for (int jj = 0; jj < 128; jj++){
        float wv = wts[jj];
        u0 += wv*g_Gt[j*256 + jj];
        u1 += wv*g_Gt[j*256 + 128 + jj];
    }
    g_u0[j] = u0; g_u1[j] = u1;
    for (int s = 64; s > 0; s >>= 1){
        if (j < s) red[j] += red[j+s];
        __syncthreads();
    }
    if (j == 0) g_Sc = red[0] + a2_b[0];
}

// s0[e]=E[e]·u0, s1[e]=E[e]·u1 (ent jobs), sq[r]=wt·Q[r] (rel jobs)
__global__ void k_sentsq(const float* __restrict__ E){
    int lane = threadIdx.x & 31;
    int warp = (blockIdx.x*blockDim.x + threadIdx.x) >> 5;
    int nw   = (gridDim.x*blockDim.x) >> 5;
    float4 u04 = ((const float4*)g_u0)[lane];
    float4 u14 = ((const float4*)g_u1)[lane];
    const float4* E4 = (const float4*)E;
    const float4* Q4 = (const float4*)g_Q;
    for (int job = warp; job < N_ENTITY + N_RELS; job += nw){
        if (job < N_ENTITY){
            float4 v = ldg4(&E4[job*32 + lane]);
            float d0 = v.x*u04.x + v.y*u04.y + v.z*u04.z + v.w*u04.w;
            float d1 = v.x*u14.x + v.y*u14.y + v.z*u14.z + v.w*u14.w;
            #pragma unroll
            for (int off = 16; off > 0; off >>= 1){
                d0 += __shfl_down_sync(0xffffffffu, d0, off);
                d1 += __shfl_down_sync(0xffffffffu, d1, off);
            }
            if (lane == 0){ g_s0[job] = d0; g_s1[job] = d1; }
        } else {
            int r = job - N_ENTITY;
            float4 w4 = ((const float4*)g_wt)[lane];
            float4 p  = Q4[r*32 + lane];
            float d0 = p.x*w4.x + p.y*w4.y + p.z*w4.z + p.w*w4.w;
            #pragma unroll
            for (int off = 16; off > 0; off >>= 1)
                d0 += __shfl_down_sync(0xffffffffu, d0, off);
            if (lane == 0) g_sq[r] = d0;
        }
    }
}

// pass D2: entity scatter (warp per 2 triplets); relation handled by CSR gather in k_rel
__global__ void k_scatter(const int* __restrict__ trip, float* __restrict__ out){
    int lane = threadIdx.x & 31;
    int warp = (blockIdx.x*blockDim.x + threadIdx.x) >> 5;
    int nw   = (gridDim.x*blockDim.x) >> 5;
    float Sc = g_Sc;
    const float4* PI4 = (const float4*)g_PI;
    const float4* Q4  = (const float4*)g_Q;
    for (int i0 = warp*2; i0 < NTRIP; i0 += nw*2){
        int i1 = i0 + 1;
        int a0 = trip[3*i0], a1 = trip[3*i0+1], a2 = trip[3*i0+2];
        int b0 = trip[3*i1], b1 = trip[3*i1+1], b2 = trip[3*i1+2];
        float sqa = __ldg(&g_sq[a2]), sqb = __ldg(&g_sq[b2]);
        float sfa = __ldg(&g_s0[a0]) + __ldg(&g_s1[a1]) + sqa + Sc;
        float sba = __ldg(&g_s0[a1]) + __ldg(&g_s1[a0]) - sqa + Sc;
        float sfb = __ldg(&g_s0[b0]) + __ldg(&g_s1[b1]) + sqb + Sc;
        float sbb = __ldg(&g_s0[b1]) + __ldg(&g_s1[b0]) - sqb + Sc;
        float efa = lrexp(sfa), eba = lrexp(sba);
        float efb = lrexp(sfb), ebb = lrexp(sbb);
        float4 pa00 = ldg4(&PI4[a0*64 + lane]);
        float4 pa10 = ldg4(&PI4[a0*64 + 32 + lane]);
        float4 pa01 = ldg4(&PI4[a1*64 + lane]);
        float4 pa11 = ldg4(&PI4[a1*64 + 32 + lane]);
        float4 qa   = ldg4(&Q4 [a2*32 + lane]);
        float4 pb00 = ldg4(&PI4[b0*64 + lane]);
        float4 pb10 = ldg4(&PI4[b0*64 + 32 + lane]);
        float4 pb01 = ldg4(&PI4[b1*64 + lane]);
        float4 pb11 = ldg4(&PI4[b1*64 + 32 + lane]);
        float4 qb   = ldg4(&Q4 [b2*32 + lane]);
        float4 zfa = f4add(f4add(pa00, pa11), qa);
        float4 zba = f4sub(f4add(pa01, pa10), qa);
        float4 zfb = f4add(f4add(pb00, pb11), qb);
        float4 zbb = f4sub(f4add(pb01, pb10), qb);
        red4(out + (size_t)a0*DIM + lane*4, f4scale(efa, zfa));
        red4(out + (size_t)a1*DIM + lane*4, f4scale(eba, zba));
        red4(out + (size_t)b0*DIM + lane*4, f4scale(efb, zfb));
        red4(out + (size_t)b1*DIM + lane*4, f4scale(ebb, zbb));
        if (lane == 0){
            atomicAdd(&g_ebs[a0], efa);
            atomicAdd(&g_ebs[a1], eba);
            atomicAdd(&g_ebs[b0], efb);
            atomicAdd(&g_ebs[b1], ebb);
        }
    }
}

__global__ void k_fin_ent(float* __restrict__ out){
    float4* O = (float4*)out;
    int i0 = blockIdx.x*blockDim.x + threadIdx.x;
    int stride = gridDim.x*blockDim.x;
    for (int idx = i0; idx < N_ENTITY*32; idx += stride){
        int e = idx >> 5, l = idx & 31;
        float ebv = g_ebs[e];
        float den = (ebv == 0.f) ? 1e-12f : ebv;
        float inv = 1.f/den;
        float4 z = O[idx];
        float4 a = ((const float4*)g_ac)[l];
        float4 d = ((const float4*)g_dc)[l];
        z.x = (a.x*z.x + d.x*ebv)*inv;
        z.y = (a.y*z.y + d.y*ebv)*inv;
        z.z = (a.z*z.z + d.z*ebv)*inv;
        z.w = (a.w*z.w + d.w*ebv)*inv;
        O[idx] = z;
    }
}

// atomic-free relation aggregation: block per relation (8 warps), CSR gather
__global__ void __launch_bounds__(256) k_rel(const int* __restrict__ trip, float* __restrict__ out){
    __shared__ float sm[8][128];
    __shared__ float sw[8];
    int r = blockIdx.x;
    int lane = threadIdx.x & 31;
    int wrp  = threadIdx.x >> 5;
    const float4* PI4 = (const float4*)g_PI;
    float4 q = ((const float4*)g_Q)[r*32 + lane];
    float sqv = g_sq[r];
    float Sc  = g_Sc;
    int base = g_offR[r], cnt = g_icntR[r];
    float4 acc = make_float4(0.f,0.f,0.f,0.f);
    float wsum = 0.f;
    for (int k = wrp; k < cnt; k += 8){
        int i = g_incR[base + k];
        int t0 = trip[3*i], t1 = trip[3*i+1];
        float s = __ldg(&g_s0[t0]) + __ldg(&g_s1[t1]) + sqv + Sc;
        float w = lrexp(s);
        float4 pa = ldg4(&PI4[t0*64 + lane]);        // P0'[t0] (d folded)
        float4 pb = ldg4(&PI4[t1*64 + 32 + lane]);   // P1[t1]
        acc.x += w*(pa.x + pb.x + q.x);
        acc.y += w*(pa.y + pb.y + q.y);
        acc.z += w*(pa.z + pb.z + q.z);
        acc.w += w*(pa.w + pb.w + q.w);
        wsum += w;
    }
    *(float4*)&sm[wrp][lane*4] = acc;
    #pragma unroll
    for (int off = 16; off > 0; off >>= 1) wsum += __shfl_down_sync(0xffffffffu, wsum, off);
    if (lane == 0) sw[wrp] = wsum;
    __syncthreads();
    int t = threadIdx.x;
    if (t < 128){
        float tot = 0.f;
        #pragma unroll
        for (int w = 0; w < 8; w++) tot += sm[w][t];
        float W = 0.f;
        #pragma unroll
        for (int w = 0; w < 8; w++) W += sw[w];
        float invc = 1.f/fmaxf((float)cnt, 1.f);
        out[OUT_ENT + (size_t)r*DIM + t] = (g_ac[t]*tot + g_dc[t]*W)*invc;
    }
}

// ---------------- launcher ----------------
extern "C" void kernel_launch(void* const* d_in, const int* in_sizes, int n_in,
                              void* d_out, int out_size){
    const int*   trip  = (const int*)  d_in[0];
    const float* E     = (const float*)d_in[1];
    const float* R     = (const float*)d_in[2];
    const float* a_w   = (const float*)d_in[3];
    const float* a_b   = (const float*)d_in[4];
    const float* a2_w  = (const float*)d_in[5];
    const float* a2_b  = (const float*)d_in[6];
    const float* bn0_g = (const float*)d_in[7];
    const float* bn0_b = (const float*)d_in[8];
    const float* bn1_g = (const float*)d_in[9];
    const float* bn1_b = (const float*)d_in[10];
    float* out = (float*)d_out;

    void *pIcE, *pIcR, *pSt, *pEbs;
    cudaGetSymbolAddress(&pIcE, g_icntE);
    cudaGetSymbolAddress(&pIcR, g_icntR);
    cudaGetSymbolAddress(&pSt,  g_stats4);
    cudaGetSymbolAddress(&pEbs, g_ebs);
    cudaMemsetAsync(pIcE, 0, N_ENTITY*sizeof(int));
    cudaMemsetAsync(pIcR, 0, N_RELS*sizeof(int));
    cudaMemsetAsync(pSt,  0, 512*sizeof(float));
    cudaMemsetAsync(pEbs, 0, N_ENTITY*sizeof(float));
    cudaMemsetAsync(out,  0, (size_t)OUT_ENT*sizeof(float));

    k_count<<<(NTRIP + 255)/256, 256>>>(trip);
    k_stats<<<1663, 128>>>(E, R);
    k_bn0makeG<<<129, 256>>>(a_w, a_b, bn0_g, bn0_b);
    k_pgemm<<<dim3(782, 2), 256>>>(E);
    k_qgemm<<<N_RELS, 128>>>(R);
    k_scanR<<<1, 512>>>();
    k_fillR<<<(NTRIP + 255)/256, 256>>>(trip);
    k_bn1stats<<<2048, 256>>>(trip);
    k_bn1fin<<<1, 128>>>(a2_w, a2_b, bn1_g, bn1_b);
    k_sentsq<<<800, 256>>>(E);
    k_scatter<<<2048, 256>>>(trip, out);
    k_fin_ent<<<2048, 256>>>(out);
    k_rel<<<N_RELS, 256>>>(trip, out);
}